// round 15
// baseline (speedup 1.0000x reference)
#include <cuda_runtime.h>
#include <cuda_bf16.h>
#include <cstdint>
#include <cstddef>

// Problem constants
#define D_MODEL 2048
#define N_HEADS 16
#define D_HEAD  128
#define WINDOW  512
#define BATCH   2
#define SEQ     4096
#define NB      (SEQ / WINDOW)
#define ROWS    (BATCH * SEQ)         // 8192
#define QKV_N   (3 * D_MODEL)         // 6144
#define KDIM    D_MODEL               // 2048
#define SCALE_F 0.08838834764831845f
#define LOG2E_F 1.4426950408889634f

// ---------------------------------------------------------------------------
// Scratch (__device__ globals; no allocation allowed)
// ---------------------------------------------------------------------------
__device__ float g_qkv[(size_t)ROWS * QKV_N];
__device__ float g_a32[(size_t)ROWS * KDIM];
__device__ float g_wq32[(size_t)QKV_N * KDIM];
__device__ float g_wo32[(size_t)D_MODEL * KDIM];

// ---------------------------------------------------------------------------
// Baseline-ISA helpers (NO tcgen05 — ptxas target is compute_103)
// ---------------------------------------------------------------------------
__device__ __forceinline__ uint32_t smem_u32(const void* p) {
    uint32_t a;
    asm("{ .reg .u64 t; cvta.to.shared.u64 t, %1; cvt.u32.u64 %0, t; }" : "=r"(a) : "l"(p));
    return a;
}
#define CP_ASYNC16(dst, src) \
    asm volatile("cp.async.cg.shared.global [%0], [%1], 16;" :: "r"(dst), "l"(src))

#define MBAR_INIT(a, c) \
    asm volatile("mbarrier.init.shared.b64 [%0], %1;" :: "r"((uint32_t)(a)), "r"((uint32_t)(c)) : "memory")
#define MBAR_ARRIVE(a) \
    asm volatile("mbarrier.arrive.shared.b64 _, [%0];" :: "r"((uint32_t)(a)) : "memory")
#define CP_ASYNC_MBAR_ARRIVE(a) \
    asm volatile("cp.async.mbarrier.arrive.noinc.shared.b64 [%0];" :: "r"((uint32_t)(a)) : "memory")
#define MBAR_WAIT(a, ph) do {                                                         \
    uint32_t _m = (uint32_t)(a); uint32_t _p = (uint32_t)(ph); uint32_t _d;           \
    asm volatile("{\n\t.reg .pred p;\n\t"                                             \
        "mbarrier.try_wait.parity.acquire.cta.shared::cta.b64 p, [%1], %2;\n\t"        \
        "selp.b32 %0, 1, 0, p;\n\t}" : "=r"(_d) : "r"(_m), "r"(_p) : "memory");        \
    if (!_d) {                                                                         \
        asm volatile("{\n\t.reg .pred P1;\n\t"                                         \
            "WL_%=:\n\t"                                                               \
            "mbarrier.try_wait.parity.acquire.cta.shared::cta.b64 P1, [%0], %1, 0x989680;\n\t" \
            "@P1 bra.uni WD_%=;\n\t"                                                   \
            "bra.uni WL_%=;\n\t"                                                       \
            "WD_%=:\n\t}" :: "r"(_m), "r"(_p) : "memory");                             \
    }                                                                                  \
} while (0)

__device__ __forceinline__ void ldmx4(uint32_t* r, uint32_t addr) {
    asm volatile("ldmatrix.sync.aligned.m8n8.x4.shared.b16 {%0,%1,%2,%3}, [%4];"
                 : "=r"(r[0]), "=r"(r[1]), "=r"(r[2]), "=r"(r[3]) : "r"(addr));
}
__device__ __forceinline__ void ldmx4t(uint32_t* r, uint32_t addr) {
    asm volatile("ldmatrix.sync.aligned.m8n8.x4.trans.shared.b16 {%0,%1,%2,%3}, [%4];"
                 : "=r"(r[0]), "=r"(r[1]), "=r"(r[2]), "=r"(r[3]) : "r"(addr));
}
__device__ __forceinline__ void mma_bf16(float* d, const uint32_t* a, const uint32_t* b) {
    asm("mma.sync.aligned.m16n8k16.row.col.f32.bf16.bf16.f32 "
        "{%0,%1,%2,%3}, {%4,%5,%6,%7}, {%8,%9}, {%0,%1,%2,%3};"
        : "+f"(d[0]), "+f"(d[1]), "+f"(d[2]), "+f"(d[3])
        : "r"(a[0]), "r"(a[1]), "r"(a[2]), "r"(a[3]), "r"(b[0]), "r"(b[1]));
}
__device__ __forceinline__ void mma_tf32(float* d, const uint32_t* a,
                                         uint32_t b0, uint32_t b1) {
    asm("mma.sync.aligned.m16n8k8.row.col.f32.tf32.tf32.f32 "
        "{%0,%1,%2,%3}, {%4,%5,%6,%7}, {%8,%9}, {%0,%1,%2,%3};"
        : "+f"(d[0]), "+f"(d[1]), "+f"(d[2]), "+f"(d[3])
        : "r"(a[0]), "r"(a[1]), "r"(a[2]), "r"(a[3]), "r"(b0), "r"(b1));
}
__device__ __forceinline__ uint32_t tf32_bits(float x) {
    uint32_t u;
    asm("cvt.rna.tf32.f32 %0, %1;" : "=r"(u) : "f"(x));
    return u;
}
__device__ __forceinline__ void split2(float a, float b, uint32_t& h, uint32_t& l) {
    __nv_bfloat16 ha = __float2bfloat16(a), hb = __float2bfloat16(b);
    __nv_bfloat162 hv(ha, hb);
    __nv_bfloat162 lv(__float2bfloat16(a - __bfloat162float(ha)),
                      __float2bfloat16(b - __bfloat162float(hb)));
    h = *(uint32_t*)&hv; l = *(uint32_t*)&lv;
}

// ---------------------------------------------------------------------------
// Conversion kernels
// ---------------------------------------------------------------------------
__global__ void cvt_tf32(const float* __restrict__ in, float* __restrict__ out, int n4)
{
    int i = blockIdx.x * blockDim.x + threadIdx.x;
    if (i >= n4) return;
    float4 v = ((const float4*)in)[i];
    uint4 o;
    o.x = tf32_bits(v.x); o.y = tf32_bits(v.y);
    o.z = tf32_bits(v.z); o.w = tf32_bits(v.w);
    ((uint4*)out)[i] = o;
}

__global__ void transpose_cvt(const float* __restrict__ W, float* __restrict__ out,
                              int K, int N)
{
    __shared__ float t[32][33];
    const int n0 = blockIdx.x * 32, k0 = blockIdx.y * 32;
    const int tx = threadIdx.x, ty = threadIdx.y;
    #pragma unroll
    for (int i = 0; i < 4; i++)
        t[ty + i * 8][tx] = W[(size_t)(k0 + ty + i * 8) * N + n0 + tx];
    __syncthreads();
    #pragma unroll
    for (int i = 0; i < 4; i++) {
        size_t o = (size_t)(n0 + ty + i * 8) * K + k0 + tx;
        ((uint32_t*)out)[o] = tf32_bits(t[tx][ty + i * 8]);
    }
}

// ---------------------------------------------------------------------------
// tf32 mma.sync GEMM, mbarrier producer/consumer pipeline, de-overheaded:
//   - k-loop unrolled by stage period 3 -> literal slot indices, no mod/wrap
//   - empty[] barrier arrivals 256 -> 8 (lane 0 per warp; warp-synchronous MMA)
//   CTA 128x128, 8 warps (64x32), BK=32, 3 slots, 2 CTAs/SM.
// ---------------------------------------------------------------------------
#define GBM 128
#define GBN 128
#define GBK 32
#define LDTF 36
#define TBUF_B (128 * LDTF * 4)            // 18432 B
#define TSTAGE_B (2 * TBUF_B)              // 36864 B
#define TNSTAGE 3
#define MB_BYTES 64
#define STAGE_OFF MB_BYTES
#define GEMM_SMEM (STAGE_OFF + TNSTAGE * TSTAGE_B)   // 110656 B (x2 <= 228K)

__device__ __forceinline__ void load_chunk(
    uint32_t sb, int slot,
    const float* __restrict__ a32, const float* __restrict__ b32,
    int bm, int bn, int k0, int tid)
{
    const uint32_t stage = sb + STAGE_OFF + (uint32_t)slot * TSTAGE_B;
    #pragma unroll
    for (int it = 0; it < 8; it++) {
        const int c = tid + it * 256;
        const int buf = c >> 10;
        const int r = (c >> 3) & 127;
        const int kc = c & 7;
        const float* src = buf ? b32 : a32;
        const int grow = (buf ? bn : bm) + r;
        const uint32_t dst = stage + buf * TBUF_B + r * (LDTF * 4) + kc * 16;
        CP_ASYNC16(dst, src + (size_t)grow * KDIM + k0 + kc * 4);
    }
}

__device__ __forceinline__ void compute_chunk(
    uint32_t sb, int slot, uint32_t a_row_off, uint32_t b_row_off,
    float d[4][4][4])
{
    const uint32_t stage = sb + STAGE_OFF + (uint32_t)slot * TSTAGE_B;
    const uint32_t abase = stage + a_row_off;
    const uint32_t bbase = stage + TBUF_B + b_row_off;
    #pragma unroll
    for (int k8 = 0; k8 < 4; k8++) {
        uint32_t ra[4][4];
        uint32_t rb[2][4];
        #pragma unroll
        for (int mf = 0; mf < 4; mf++)
            ldmx4(ra[mf], abase + (uint32_t)(mf * 16) * (LDTF * 4) + k8 * 32);
        #pragma unroll
        for (int nf2 = 0; nf2 < 2; nf2++)
            ldmx4(rb[nf2], bbase + (uint32_t)(nf2 * 16) * (LDTF * 4) + k8 * 32);
        #pragma unroll
        for (int mf = 0; mf < 4; mf++)
            #pragma unroll
            for (int nf = 0; nf < 4; nf++)
                mma_tf32(d[mf][nf], ra[mf],
                         rb[nf >> 1][nf & 1], rb[nf >> 1][(nf & 1) + 2]);
    }
}

// one pipeline iteration: load chunk kt+2 into slot sC (empty parity phE),
// then wait full[sK] parity phF, compute, lane0 arrives empty[sK].
__device__ __forceinline__ void gemm_iter(
    uint32_t sb, int kt, int nk, int sC, int phE, int sK, int phF,
    const float* __restrict__ a32, const float* __restrict__ b32,
    int bm, int bn, int tid, int lane,
    uint32_t a_row_off, uint32_t b_row_off, float d[4][4][4])
{
    const int c = kt + 2;
    if (c < nk) {
        if (c >= TNSTAGE)
            MBAR_WAIT(sb + 24 + sC * 8, phE);
        load_chunk(sb, sC, a32, b32, bm, bn, c * GBK, tid);
        CP_ASYNC_MBAR_ARRIVE(sb + sC * 8);
    }
    MBAR_WAIT(sb + sK * 8, phF);
    compute_chunk(sb, sK, a_row_off, b_row_off, d);
    if (lane == 0)
        MBAR_ARRIVE(sb + 24 + sK * 8);
}

__global__ __launch_bounds__(256, 2)
void gemm_tf32_kernel(const float* __restrict__ a32, const float* __restrict__ b32,
                      const float* __restrict__ bias, float* __restrict__ C, int N)
{
    extern __shared__ char smem[];
    const uint32_t sb = smem_u32(smem);
    const int tid = threadIdx.x;
    const int wid = tid >> 5;
    const int lane = tid & 31;
    const int bm = blockIdx.y * GBM;
    const int bn = blockIdx.x * GBN;
    const int warp_m = (wid >> 2) * 64;
    const int warp_n = (wid & 3) * 32;

    // full[s] @ sb+s*8 (count 256 cp.async arrives); empty[s] @ sb+24+s*8 (count 8)
    if (tid == 0) {
        #pragma unroll
        for (int s = 0; s < TNSTAGE; s++) {
            MBAR_INIT(sb + s * 8, 256);
            MBAR_INIT(sb + 24 + s * 8, 8);
        }
    }
    __syncthreads();

    float d[4][4][4];
    #pragma unroll
    for (int i = 0; i < 4; i++)
        #pragma unroll
        for (int j = 0; j < 4; j++)
            #pragma unroll
            for (int r = 0; r < 4; r++) d[i][j][r] = 0.0f;

    const int nk = KDIM / GBK;  // 64

    load_chunk(sb, 0, a32, b32, bm, bn, 0, tid);
    CP_ASYNC_MBAR_ARRIVE(sb + 0 * 8);
    load_chunk(sb, 1, a32, b32, bm, bn, GBK, tid);
    CP_ASYNC_MBAR_ARRIVE(sb + 1 * 8);

    const uint32_t a_row_off = (uint32_t)(warp_m + (lane & 15)) * (LDTF * 4)
                             + ((lane >> 4) << 4);
    const uint32_t b_row_off = (uint32_t)(warp_n + (lane & 15)) * (LDTF * 4)
                             + ((lane >> 4) << 4);

    // 21 groups of 3 (kt = 0..62), literal slots; remainder kt = 63 (slot 0).
    // chunk kt consumed at full parity (kt/3)&1 = g&1.
    // loader chunk kt+2: slots (2,0,1) for j=(0,1,2); empty parity (c/3-1)&1.
    for (int g = 0; g < 21; g++) {
        const int kt = 3 * g;
        const int pg = g & 1;
        const int pgm = (g - 1) & 1;
        gemm_iter(sb, kt + 0, nk, 2, pgm, 0, pg,
                  a32, b32, bm, bn, tid, lane, a_row_off, b_row_off, d);
        gemm_iter(sb, kt + 1, nk, 0, pg, 1, pg,
                  a32, b32, bm, bn, tid, lane, a_row_off, b_row_off, d);
        gemm_iter(sb, kt + 2, nk, 1, pg, 2, pg,
                  a32, b32, bm, bn, tid, lane, a_row_off, b_row_off, d);
    }
    // kt = 63: slot 0, full parity (63/3)&1 = 1; no load (chunk 65 >= nk)
    gemm_iter(sb, 63, nk, 2, 0, 0, 1,
              a32, b32, bm, bn, tid, lane, a_row_off, b_row_off, d);

    #pragma unroll
    for (int nf = 0; nf < 4; nf++) {
        const int c0 = bn + warp_n + nf * 8 + (lane & 3) * 2;
        const float b0 = bias[c0], b1 = bias[c0 + 1];
        #pragma unroll
        for (int mf = 0; mf < 4; mf++) {
            const int r0 = bm + warp_m + mf * 16 + (lane >> 2);
            float2 v0, v1;
            v0.x = d[mf][nf][0] + b0; v0.y = d[mf][nf][1] + b1;
            v1.x = d[mf][nf][2] + b0; v1.y = d[mf][nf][3] + b1;
            *(float2*)&C[(size_t)r0 * N + c0]       = v0;
            *(float2*)&C[(size_t)(r0 + 8) * N + c0] = v1;
        }
    }
}

// ---------------------------------------------------------------------------
// Tensor-core windowed causal flash attention (3-term split-bf16, proven).
// ---------------------------------------------------------------------------
#define SQE 136
#define SQB (SQE * 2)
#define ATILE_B (64 * SQB)
#define ATTN_SMEM (4 * ATILE_B)

__device__ __forceinline__ void load_conv(char* hi, char* lo, const float* __restrict__ src)
{
    const int tid = threadIdx.x;
    #pragma unroll
    for (int it = 0; it < 16; it++) {
        const int lin = tid + it * 128;
        const int r = lin >> 5;
        const int c = (lin & 31) * 4;
        float4 v = *(const float4*)&src[(size_t)r * QKV_N + c];
        uint32_t h0, l0, h1, l1;
        split2(v.x, v.y, h0, l0);
        split2(v.z, v.w, h1, l1);
        const int byte = r * SQB + c * 2;
        *(uint32_t*)(hi + byte)     = h0;
        *(uint32_t*)(hi + byte + 4) = h1;
        *(uint32_t*)(lo + byte)     = l0;
        *(uint32_t*)(lo + byte + 4) = l1;
    }
}

__global__ __launch_bounds__(128)
void attn_mma_kernel(const float* __restrict__ qkv, float* __restrict__ oatt)
{
    extern __shared__ char asmem[];
    char* QHI = asmem;
    char* QLO = asmem + ATILE_B;
    char* KVH = asmem + 2 * ATILE_B;
    char* KVL = asmem + 3 * ATILE_B;
    const uint32_t sb = smem_u32(asmem);
    const uint32_t KVH_U = sb + 2 * ATILE_B;
    const uint32_t KVL_U = sb + 3 * ATILE_B;

    const int tid = threadIdx.x;
    const int wid = tid >> 5;
    const int lane = tid & 31;
    const int qb = blockIdx.x;
    const int n  = blockIdx.y;
    const int bh = blockIdx.z;
    const int b  = bh >> 4;
    const int h  = bh & 15;

    const size_t row0 = (size_t)b * SEQ + (size_t)n * WINDOW;
    const float* qptr = qkv + (row0 + qb * 64) * QKV_N + h * D_HEAD;
    const float* kbase = qkv + row0 * QKV_N + h * D_HEAD + D_MODEL;
    const float* vbase = qkv + row0 * QKV_N + h * D_HEAD + 2 * D_MODEL;

    load_conv(QHI, QLO, qptr);

    const int warp_m = wid * 16;
    const int r0 = lane >> 2;
    const int qq = lane & 3;

    float o[16][4];
    #pragma unroll
    for (int j = 0; j < 16; j++)
        #pragma unroll
        for (int r = 0; r < 4; r++) o[j][r] = 0.0f;
    float m0 = -1e30f, m1 = -1e30f, l0 = 0.0f, l1 = 0.0f;

    for (int jt = 0; jt <= qb; jt++) {
        __syncthreads();
        load_conv(KVH, KVL, kbase + (size_t)(jt * 64) * QKV_N);
        __syncthreads();

        float s[8][4];
        #pragma unroll
        for (int j = 0; j < 8; j++)
            #pragma unroll
            for (int r = 0; r < 4; r++) s[j][r] = 0.0f;

        #pragma unroll
        for (int k16 = 0; k16 < 8; k16++) {
            uint32_t ra[2][4], rb[2][4][4];
            #pragma unroll
            for (int hl = 0; hl < 2; hl++) {
                const uint32_t ab = sb + (hl ? ATILE_B : 0u);
                ldmx4(ra[hl], ab + (warp_m + (lane & 15)) * SQB
                                 + (((lane >> 4) << 3) + k16 * 16) * 2);
                const uint32_t bb = hl ? KVL_U : KVH_U;
                #pragma unroll
                for (int g = 0; g < 4; g++) {
                    const int row = g * 16 + ((lane >> 4) << 3) + (lane & 7);
                    const int col = (((lane >> 3) & 1) << 3) + k16 * 16;
                    ldmx4(rb[hl][g], bb + row * SQB + col * 2);
                }
            }
            #pragma unroll
            for (int t = 0; t < 3; t++) {
                const int ah = (t == 2) ? 1 : 0;
                const int bl = (t == 1) ? 1 : 0;
                #pragma unroll
                for (int j = 0; j < 8; j++)
                    mma_bf16(s[j], ra[ah], &rb[bl][j >> 1][(j & 1) * 2]);
            }
        }

        const int rg0 = warp_m + r0;
        #pragma unroll
        for (int j = 0; j < 8; j++)
            #pragma unroll
            for (int r = 0; r < 4; r++) s[j][r] *= SCALE_F;
        if (jt == qb) {
            #pragma unroll
            for (int j = 0; j < 8; j++) {
                const int c0 = j * 8 + qq * 2;
                if (c0     > rg0)     s[j][0] = -1e30f;
                if (c0 + 1 > rg0)     s[j][1] = -1e30f;
                if (c0     > rg0 + 8) s[j][2] = -1e30f;
                if (c0 + 1 > rg0 + 8) s[j][3] = -1e30f;
            }
        }

        float mx0 = -1e30f, mx1 = -1e30f;
        #pragma unroll
        for (int j = 0; j < 8; j++) {
            mx0 = fmaxf(mx0, fmaxf(s[j][0], s[j][1]));
            mx1 = fmaxf(mx1, fmaxf(s[j][2], s[j][3]));
        }
        #pragma unroll
        for (int off = 1; off < 4; off <<= 1) {
            mx0 = fmaxf(mx0, __shfl_xor_sync(0xffffffffu, mx0, off));
            mx1 = fmaxf(mx1, __shfl_xor_sync(0xffffffffu, mx1, off));
        }
        const float mn0 = fmaxf(m0, mx0), mn1 = fmaxf(m1, mx1);
        const float f0 = exp2f((m0 - mn0) * LOG2E_F);
        const float f1 = exp2f((m1 - mn1) * LOG2E_F);
        float rs0 = 0.0f, rs1 = 0.0f;
        #pragma unroll
        for (int j = 0; j < 8; j++) {
            s[j][0] = exp2f((s[j][0] - mn0) * LOG2E_F); rs0 += s[j][0];
            s[j][1] = exp2f((s[j][1] - mn0) * LOG2E_F); rs0 += s[j][1];
            s[j][2] = exp2f((s[j][2] - mn1) * LOG2E_F); rs1 += s[j][2];
            s[j][3] = exp2f((s[j][3] - mn1) * LOG2E_F); rs1 += s[j][3];
        }
        #pragma unroll
        for (int off = 1; off < 4; off <<= 1) {
            rs0 += __shfl_xor_sync(0xffffffffu, rs0, off);
            rs1 += __shfl_xor_sync(0xffffffffu, rs1, off);
        }
        l0 = l0 * f0 + rs0; m0 = mn0;
        l1 = l1 * f1 + rs1; m1 = mn1;
        #pragma unroll
        for (int j = 0; j < 16; j++) {
            o[j][0] *= f0; o[j][1] *= f0;
            o[j][2] *= f1; o[j][3] *= f1;
        }

        uint32_t pah[4][4], pal[4][4];
        #pragma unroll
        for (int kc = 0; kc < 4; kc++) {
            split2(s[2 * kc][0],     s[2 * kc][1],     pah[kc][0], pal[kc][0]);
            split2(s[2 * kc][2],     s[2 * kc][3],     pah[kc][1], pal[kc][1]);
            split2(s[2 * kc + 1][0], s[2 * kc + 1][1], pah[kc][2], pal[kc][2]);
            split2(s[2 * kc + 1][2], s[2 * kc + 1][3], pah[kc][3], pal[kc][3]);
        }

        __syncthreads();
        load_conv(KVH, KVL, vbase + (size_t)(jt * 64) * QKV_N);
        __syncthreads();

        const int vrow_part = ((lane >> 3) & 1) * 8 + (lane & 7);
        const int vcol_part = (lane >> 4) * 8;
        #pragma unroll
        for (int kc = 0; kc < 4; kc++) {
            #pragma unroll
            for (int d16 = 0; d16 < 8; d16++) {
                uint32_t vh[4], vl[4];
                const uint32_t off = (kc * 16 + vrow_part) * SQB + (d16 * 16 + vcol_part) * 2;
                ldmx4t(vh, KVH_U + off);
                ldmx4t(vl, KVL_U + off);
                mma_bf16(o[2 * d16],     pah[kc], &vh[0]);
                mma_bf16(o[2 * d16 + 1], pah[kc], &vh[2]);
                mma_bf16(o[2 * d16],     pah[kc], &vl[0]);
                mma_bf16(o[2 * d16 + 1], pah[kc], &vl[2]);
                mma_bf16(o[2 * d16],     pal[kc], &vh[0]);
                mma_bf16(o[2 * d16 + 1], pal[kc], &vh[2]);
            }
        }
    }

    const float inv0 = 1.0f / l0, inv1 = 1.0f / l1;
    const size_t gr0 = row0 + qb * 64 + warp_m + r0;
    const size_t gr1 = gr0 + 8;
    #pragma unroll
    for (int j = 0; j < 16; j++) {
        const int col = h * D_HEAD + j * 8 + qq * 2;
        uint2 v0, v1;
        v0.x = tf32_bits(o[j][0] * inv0); v0.y = tf32_bits(o[j][1] * inv0);
        v1.x = tf32_bits(o[j][2] * inv1); v1.y = tf32_bits(o[j][3] * inv1);
        *(uint2*)&((uint32_t*)oatt)[gr0 * KDIM + col] = v0;
        *(uint2*)&((uint32_t*)oatt)[gr1 * KDIM + col] = v1;
    }
}

// ---------------------------------------------------------------------------
extern "C" void kernel_launch(void* const* d_in, const int* in_sizes, int n_in,
                              void* d_out, int out_size)
{
    const float* x    = (const float*)d_in[0];
    const float* Wqkv = (const float*)d_in[1];
    const float* bqkv = (const float*)d_in[2];
    const float* Wout = (const float*)d_in[3];
    const float* bout = (const float*)d_in[4];
    float* out = (float*)d_out;

    float *qkv, *a32, *wq32, *wo32;
    cudaGetSymbolAddress((void**)&qkv,  g_qkv);
    cudaGetSymbolAddress((void**)&a32,  g_a32);
    cudaGetSymbolAddress((void**)&wq32, g_wq32);
    cudaGetSymbolAddress((void**)&wo32, g_wo32);

    cudaFuncSetAttribute(gemm_tf32_kernel,
                         cudaFuncAttributeMaxDynamicSharedMemorySize, GEMM_SMEM);
    cudaFuncSetAttribute(attn_mma_kernel,
                         cudaFuncAttributeMaxDynamicSharedMemorySize, ATTN_SMEM);

    transpose_cvt<<<dim3(QKV_N / 32, KDIM / 32), dim3(32, 8)>>>(Wqkv, wq32, KDIM, QKV_N);
    transpose_cvt<<<dim3(D_MODEL / 32, KDIM / 32), dim3(32, 8)>>>(Wout, wo32, KDIM, D_MODEL);

    {
        const int n4 = ROWS * D_MODEL / 4;
        cvt_tf32<<<(n4 + 255) / 256, 256>>>(x, a32, n4);
    }
    gemm_tf32_kernel<<<dim3(QKV_N / GBN, ROWS / GBM), 256, GEMM_SMEM>>>(
        a32, wq32, bqkv, qkv, QKV_N);

    attn_mma_kernel<<<dim3(WINDOW / 64, NB, BATCH * N_HEADS), 128, ATTN_SMEM>>>(qkv, a32);

    gemm_tf32_kernel<<<dim3(D_MODEL / GBN, ROWS / GBM), 256, GEMM_SMEM>>>(
        a32, wo32, bout, out, D_MODEL);
}

// round 16
// speedup vs baseline: 1.0691x; 1.0691x over previous
#include <cuda_runtime.h>
#include <cuda_bf16.h>
#include <cstdint>
#include <cstddef>

// Problem constants
#define D_MODEL 2048
#define N_HEADS 16
#define D_HEAD  128
#define WINDOW  512
#define BATCH   2
#define SEQ     4096
#define NB      (SEQ / WINDOW)
#define ROWS    (BATCH * SEQ)         // 8192
#define QKV_N   (3 * D_MODEL)         // 6144
#define KDIM    D_MODEL               // 2048
#define SCALE_F 0.08838834764831845f
#define LOG2E_F 1.4426950408889634f

// ---------------------------------------------------------------------------
// Scratch (__device__ globals; no allocation allowed)
// ---------------------------------------------------------------------------
__device__ float g_qkv[(size_t)ROWS * QKV_N];
__device__ float g_a32[(size_t)ROWS * KDIM];
__device__ float g_wq32[(size_t)QKV_N * KDIM];
__device__ float g_wo32[(size_t)D_MODEL * KDIM];

// ---------------------------------------------------------------------------
// Baseline-ISA helpers (NO tcgen05 — ptxas target is compute_103)
// ---------------------------------------------------------------------------
__device__ __forceinline__ uint32_t smem_u32(const void* p) {
    uint32_t a;
    asm("{ .reg .u64 t; cvta.to.shared.u64 t, %1; cvt.u32.u64 %0, t; }" : "=r"(a) : "l"(p));
    return a;
}
#define CP_ASYNC16(dst, src) \
    asm volatile("cp.async.cg.shared.global [%0], [%1], 16;" :: "r"(dst), "l"(src))

#define MBAR_INIT(a, c) \
    asm volatile("mbarrier.init.shared.b64 [%0], %1;" :: "r"((uint32_t)(a)), "r"((uint32_t)(c)) : "memory")
#define MBAR_ARRIVE(a) \
    asm volatile("mbarrier.arrive.shared.b64 _, [%0];" :: "r"((uint32_t)(a)) : "memory")
#define CP_ASYNC_MBAR_ARRIVE(a) \
    asm volatile("cp.async.mbarrier.arrive.noinc.shared.b64 [%0];" :: "r"((uint32_t)(a)) : "memory")
#define MBAR_WAIT(a, ph) do {                                                         \
    uint32_t _m = (uint32_t)(a); uint32_t _p = (uint32_t)(ph); uint32_t _d;           \
    asm volatile("{\n\t.reg .pred p;\n\t"                                             \
        "mbarrier.try_wait.parity.acquire.cta.shared::cta.b64 p, [%1], %2;\n\t"        \
        "selp.b32 %0, 1, 0, p;\n\t}" : "=r"(_d) : "r"(_m), "r"(_p) : "memory");        \
    if (!_d) {                                                                         \
        asm volatile("{\n\t.reg .pred P1;\n\t"                                         \
            "WL_%=:\n\t"                                                               \
            "mbarrier.try_wait.parity.acquire.cta.shared::cta.b64 P1, [%0], %1, 0x989680;\n\t" \
            "@P1 bra.uni WD_%=;\n\t"                                                   \
            "bra.uni WL_%=;\n\t"                                                       \
            "WD_%=:\n\t}" :: "r"(_m), "r"(_p) : "memory");                             \
    }                                                                                  \
} while (0)

__device__ __forceinline__ void ldmx4(uint32_t* r, uint32_t addr) {
    asm volatile("ldmatrix.sync.aligned.m8n8.x4.shared.b16 {%0,%1,%2,%3}, [%4];"
                 : "=r"(r[0]), "=r"(r[1]), "=r"(r[2]), "=r"(r[3]) : "r"(addr));
}
__device__ __forceinline__ void ldmx4t(uint32_t* r, uint32_t addr) {
    asm volatile("ldmatrix.sync.aligned.m8n8.x4.trans.shared.b16 {%0,%1,%2,%3}, [%4];"
                 : "=r"(r[0]), "=r"(r[1]), "=r"(r[2]), "=r"(r[3]) : "r"(addr));
}
__device__ __forceinline__ void mma_bf16(float* d, const uint32_t* a, const uint32_t* b) {
    asm("mma.sync.aligned.m16n8k16.row.col.f32.bf16.bf16.f32 "
        "{%0,%1,%2,%3}, {%4,%5,%6,%7}, {%8,%9}, {%0,%1,%2,%3};"
        : "+f"(d[0]), "+f"(d[1]), "+f"(d[2]), "+f"(d[3])
        : "r"(a[0]), "r"(a[1]), "r"(a[2]), "r"(a[3]), "r"(b[0]), "r"(b[1]));
}
__device__ __forceinline__ void mma_tf32(float* d, const uint32_t* a,
                                         uint32_t b0, uint32_t b1) {
    asm("mma.sync.aligned.m16n8k8.row.col.f32.tf32.tf32.f32 "
        "{%0,%1,%2,%3}, {%4,%5,%6,%7}, {%8,%9}, {%0,%1,%2,%3};"
        : "+f"(d[0]), "+f"(d[1]), "+f"(d[2]), "+f"(d[3])
        : "r"(a[0]), "r"(a[1]), "r"(a[2]), "r"(a[3]), "r"(b0), "r"(b1));
}
__device__ __forceinline__ uint32_t tf32_bits(float x) {
    uint32_t u;
    asm("cvt.rna.tf32.f32 %0, %1;" : "=r"(u) : "f"(x));
    return u;
}
__device__ __forceinline__ void split2(float a, float b, uint32_t& h, uint32_t& l) {
    __nv_bfloat16 ha = __float2bfloat16(a), hb = __float2bfloat16(b);
    __nv_bfloat162 hv(ha, hb);
    __nv_bfloat162 lv(__float2bfloat16(a - __bfloat162float(ha)),
                      __float2bfloat16(b - __bfloat162float(hb)));
    h = *(uint32_t*)&hv; l = *(uint32_t*)&lv;
}

// ---------------------------------------------------------------------------
// Conversion kernels
// ---------------------------------------------------------------------------
__global__ void cvt_tf32(const float* __restrict__ in, float* __restrict__ out, int n4)
{
    int i = blockIdx.x * blockDim.x + threadIdx.x;
    if (i >= n4) return;
    float4 v = ((const float4*)in)[i];
    uint4 o;
    o.x = tf32_bits(v.x); o.y = tf32_bits(v.y);
    o.z = tf32_bits(v.z); o.w = tf32_bits(v.w);
    ((uint4*)out)[i] = o;
}

__global__ void transpose_cvt(const float* __restrict__ W, float* __restrict__ out,
                              int K, int N)
{
    __shared__ float t[32][33];
    const int n0 = blockIdx.x * 32, k0 = blockIdx.y * 32;
    const int tx = threadIdx.x, ty = threadIdx.y;
    #pragma unroll
    for (int i = 0; i < 4; i++)
        t[ty + i * 8][tx] = W[(size_t)(k0 + ty + i * 8) * N + n0 + tx];
    __syncthreads();
    #pragma unroll
    for (int i = 0; i < 4; i++) {
        size_t o = (size_t)(n0 + ty + i * 8) * K + k0 + tx;
        ((uint32_t*)out)[o] = tf32_bits(t[tx][ty + i * 8]);
    }
}

// ---------------------------------------------------------------------------
// tf32 mma.sync GEMM, mbarrier producer/consumer pipeline (R14 structure).
//   ONE change vs R14: empty[] arrivals 256 -> 8 (lane 0 per warp;
//   mma.sync/ldmatrix are warp-synchronous so lane0 done => warp done).
//   CTA 128x128, 8 warps (64x32), BK=32, 3 slots, 2 CTAs/SM.
// ---------------------------------------------------------------------------
#define GBM 128
#define GBN 128
#define GBK 32
#define LDTF 36                            // floats/row (32 + 4 pad); 144 B
#define TBUF_B (128 * LDTF * 4)            // 18432 B per A or B tile
#define TSTAGE_B (2 * TBUF_B)              // 36864 B
#define TNSTAGE 3
#define MB_BYTES 64                        // full[3] @0, empty[3] @24 (+pad)
#define STAGE_OFF MB_BYTES
#define GEMM_SMEM (STAGE_OFF + TNSTAGE * TSTAGE_B)   // 110656 B (x2 <= 228K)

__device__ __forceinline__ void load_chunk(
    uint32_t sb, int slot,
    const float* __restrict__ a32, const float* __restrict__ b32,
    int bm, int bn, int k0, int tid)
{
    const uint32_t stage = sb + STAGE_OFF + (uint32_t)slot * TSTAGE_B;
    #pragma unroll
    for (int it = 0; it < 8; it++) {
        const int c = tid + it * 256;
        const int buf = c >> 10;            // 0=A 1=B
        const int r = (c >> 3) & 127;
        const int kc = c & 7;
        const float* src = buf ? b32 : a32;
        const int grow = (buf ? bn : bm) + r;
        const uint32_t dst = stage + buf * TBUF_B + r * (LDTF * 4) + kc * 16;
        CP_ASYNC16(dst, src + (size_t)grow * KDIM + k0 + kc * 4);
    }
}

__global__ __launch_bounds__(256, 2)
void gemm_tf32_kernel(const float* __restrict__ a32, const float* __restrict__ b32,
                      const float* __restrict__ bias, float* __restrict__ C, int N)
{
    extern __shared__ char smem[];
    const uint32_t sb = smem_u32(smem);
    const int tid = threadIdx.x;
    const int wid = tid >> 5;
    const int lane = tid & 31;
    const int bm = blockIdx.y * GBM;
    const int bn = blockIdx.x * GBN;
    const int warp_m = (wid >> 2) * 64;   // 0 or 64
    const int warp_n = (wid & 3) * 32;    // 0,32,64,96

    // full[s] = 256 async arrives; empty[s] = 8 (lane 0 of each warp)
    if (tid == 0) {
        #pragma unroll
        for (int s = 0; s < TNSTAGE; s++) {
            MBAR_INIT(sb + s * 8, 256);
            MBAR_INIT(sb + 24 + s * 8, 8);
        }
    }
    __syncthreads();

    float d[4][4][4];                     // 64 accums
    #pragma unroll
    for (int i = 0; i < 4; i++)
        #pragma unroll
        for (int j = 0; j < 4; j++)
            #pragma unroll
            for (int r = 0; r < 4; r++) d[i][j][r] = 0.0f;

    const int nk = KDIM / GBK;  // 64

    // prologue: chunks 0,1 -> slots 0,1
    load_chunk(sb, 0, a32, b32, bm, bn, 0, tid);
    CP_ASYNC_MBAR_ARRIVE(sb + 0 * 8);
    load_chunk(sb, 1, a32, b32, bm, bn, GBK, tid);
    CP_ASYNC_MBAR_ARRIVE(sb + 1 * 8);

    const uint32_t a_row_off = (uint32_t)(warp_m + (lane & 15)) * (LDTF * 4)
                             + ((lane >> 4) << 4);
    const uint32_t b_row_off = (uint32_t)(warp_n + (lane & 15)) * (LDTF * 4)
                             + ((lane >> 4) << 4);

    // loader state: next chunk c (starts at 2), its slot cs, euse = c/3
    int c = 2, cs = 2, euse = 0;
    // consumer state: chunk kt slot s, use = kt/3
    int s = 0, use = 0;

    for (int kt = 0; kt < nk; kt++) {
        // ---- issue loads for chunk kt+2 ----
        if (c < nk) {
            if (c >= TNSTAGE)
                MBAR_WAIT(sb + 24 + cs * 8, (euse - 1) & 1);   // slot free
            load_chunk(sb, cs, a32, b32, bm, bn, c * GBK, tid);
            CP_ASYNC_MBAR_ARRIVE(sb + cs * 8);
            c++; cs++; if (cs == TNSTAGE) { cs = 0; euse++; }
        }

        // ---- wait for chunk kt data ----
        MBAR_WAIT(sb + s * 8, use & 1);

        const uint32_t stage = sb + STAGE_OFF + (uint32_t)s * TSTAGE_B;
        const uint32_t abase = stage + a_row_off;
        const uint32_t bbase = stage + TBUF_B + b_row_off;

        #pragma unroll
        for (int k8 = 0; k8 < 4; k8++) {
            uint32_t ra[4][4];
            uint32_t rb[2][4];
            #pragma unroll
            for (int mf = 0; mf < 4; mf++)
                ldmx4(ra[mf], abase + (uint32_t)(mf * 16) * (LDTF * 4) + k8 * 32);
            #pragma unroll
            for (int nf2 = 0; nf2 < 2; nf2++)
                ldmx4(rb[nf2], bbase + (uint32_t)(nf2 * 16) * (LDTF * 4) + k8 * 32);
            #pragma unroll
            for (int mf = 0; mf < 4; mf++)
                #pragma unroll
                for (int nf = 0; nf < 4; nf++)
                    mma_tf32(d[mf][nf], ra[mf],
                             rb[nf >> 1][nf & 1], rb[nf >> 1][(nf & 1) + 2]);
        }

        if (lane == 0)
            MBAR_ARRIVE(sb + 24 + s * 8);  // warp done reading slot s
        s++; if (s == TNSTAGE) { s = 0; use++; }
    }

    #pragma unroll
    for (int nf = 0; nf < 4; nf++) {
        const int c0 = bn + warp_n + nf * 8 + (lane & 3) * 2;
        const float b0 = bias[c0], b1 = bias[c0 + 1];
        #pragma unroll
        for (int mf = 0; mf < 4; mf++) {
            const int r0 = bm + warp_m + mf * 16 + (lane >> 2);
            float2 v0, v1;
            v0.x = d[mf][nf][0] + b0; v0.y = d[mf][nf][1] + b1;
            v1.x = d[mf][nf][2] + b0; v1.y = d[mf][nf][3] + b1;
            *(float2*)&C[(size_t)r0 * N + c0]       = v0;
            *(float2*)&C[(size_t)(r0 + 8) * N + c0] = v1;
        }
    }
}

// ---------------------------------------------------------------------------
// Tensor-core windowed causal flash attention (3-term split-bf16, proven).
// ---------------------------------------------------------------------------
#define SQE 136
#define SQB (SQE * 2)
#define ATILE_B (64 * SQB)
#define ATTN_SMEM (4 * ATILE_B)

__device__ __forceinline__ void load_conv(char* hi, char* lo, const float* __restrict__ src)
{
    const int tid = threadIdx.x;
    #pragma unroll
    for (int it = 0; it < 16; it++) {
        const int lin = tid + it * 128;
        const int r = lin >> 5;
        const int c = (lin & 31) * 4;
        float4 v = *(const float4*)&src[(size_t)r * QKV_N + c];
        uint32_t h0, l0, h1, l1;
        split2(v.x, v.y, h0, l0);
        split2(v.z, v.w, h1, l1);
        const int byte = r * SQB + c * 2;
        *(uint32_t*)(hi + byte)     = h0;
        *(uint32_t*)(hi + byte + 4) = h1;
        *(uint32_t*)(lo + byte)     = l0;
        *(uint32_t*)(lo + byte + 4) = l1;
    }
}

__global__ __launch_bounds__(128)
void attn_mma_kernel(const float* __restrict__ qkv, float* __restrict__ oatt)
{
    extern __shared__ char asmem[];
    char* QHI = asmem;
    char* QLO = asmem + ATILE_B;
    char* KVH = asmem + 2 * ATILE_B;
    char* KVL = asmem + 3 * ATILE_B;
    const uint32_t sb = smem_u32(asmem);
    const uint32_t KVH_U = sb + 2 * ATILE_B;
    const uint32_t KVL_U = sb + 3 * ATILE_B;

    const int tid = threadIdx.x;
    const int wid = tid >> 5;
    const int lane = tid & 31;
    const int qb = blockIdx.x;
    const int n  = blockIdx.y;
    const int bh = blockIdx.z;
    const int b  = bh >> 4;
    const int h  = bh & 15;

    const size_t row0 = (size_t)b * SEQ + (size_t)n * WINDOW;
    const float* qptr = qkv + (row0 + qb * 64) * QKV_N + h * D_HEAD;
    const float* kbase = qkv + row0 * QKV_N + h * D_HEAD + D_MODEL;
    const float* vbase = qkv + row0 * QKV_N + h * D_HEAD + 2 * D_MODEL;

    load_conv(QHI, QLO, qptr);

    const int warp_m = wid * 16;
    const int r0 = lane >> 2;
    const int qq = lane & 3;

    float o[16][4];
    #pragma unroll
    for (int j = 0; j < 16; j++)
        #pragma unroll
        for (int r = 0; r < 4; r++) o[j][r] = 0.0f;
    float m0 = -1e30f, m1 = -1e30f, l0 = 0.0f, l1 = 0.0f;

    for (int jt = 0; jt <= qb; jt++) {
        __syncthreads();
        load_conv(KVH, KVL, kbase + (size_t)(jt * 64) * QKV_N);
        __syncthreads();

        float s[8][4];
        #pragma unroll
        for (int j = 0; j < 8; j++)
            #pragma unroll
            for (int r = 0; r < 4; r++) s[j][r] = 0.0f;

        #pragma unroll
        for (int k16 = 0; k16 < 8; k16++) {
            uint32_t ra[2][4], rb[2][4][4];
            #pragma unroll
            for (int hl = 0; hl < 2; hl++) {
                const uint32_t ab = sb + (hl ? ATILE_B : 0u);
                ldmx4(ra[hl], ab + (warp_m + (lane & 15)) * SQB
                                 + (((lane >> 4) << 3) + k16 * 16) * 2);
                const uint32_t bb = hl ? KVL_U : KVH_U;
                #pragma unroll
                for (int g = 0; g < 4; g++) {
                    const int row = g * 16 + ((lane >> 4) << 3) + (lane & 7);
                    const int col = (((lane >> 3) & 1) << 3) + k16 * 16;
                    ldmx4(rb[hl][g], bb + row * SQB + col * 2);
                }
            }
            #pragma unroll
            for (int t = 0; t < 3; t++) {
                const int ah = (t == 2) ? 1 : 0;
                const int bl = (t == 1) ? 1 : 0;
                #pragma unroll
                for (int j = 0; j < 8; j++)
                    mma_bf16(s[j], ra[ah], &rb[bl][j >> 1][(j & 1) * 2]);
            }
        }

        const int rg0 = warp_m + r0;
        #pragma unroll
        for (int j = 0; j < 8; j++)
            #pragma unroll
            for (int r = 0; r < 4; r++) s[j][r] *= SCALE_F;
        if (jt == qb) {
            #pragma unroll
            for (int j = 0; j < 8; j++) {
                const int c0 = j * 8 + qq * 2;
                if (c0     > rg0)     s[j][0] = -1e30f;
                if (c0 + 1 > rg0)     s[j][1] = -1e30f;
                if (c0     > rg0 + 8) s[j][2] = -1e30f;
                if (c0 + 1 > rg0 + 8) s[j][3] = -1e30f;
            }
        }

        float mx0 = -1e30f, mx1 = -1e30f;
        #pragma unroll
        for (int j = 0; j < 8; j++) {
            mx0 = fmaxf(mx0, fmaxf(s[j][0], s[j][1]));
            mx1 = fmaxf(mx1, fmaxf(s[j][2], s[j][3]));
        }
        #pragma unroll
        for (int off = 1; off < 4; off <<= 1) {
            mx0 = fmaxf(mx0, __shfl_xor_sync(0xffffffffu, mx0, off));
            mx1 = fmaxf(mx1, __shfl_xor_sync(0xffffffffu, mx1, off));
        }
        const float mn0 = fmaxf(m0, mx0), mn1 = fmaxf(m1, mx1);
        const float f0 = exp2f((m0 - mn0) * LOG2E_F);
        const float f1 = exp2f((m1 - mn1) * LOG2E_F);
        float rs0 = 0.0f, rs1 = 0.0f;
        #pragma unroll
        for (int j = 0; j < 8; j++) {
            s[j][0] = exp2f((s[j][0] - mn0) * LOG2E_F); rs0 += s[j][0];
            s[j][1] = exp2f((s[j][1] - mn0) * LOG2E_F); rs0 += s[j][1];
            s[j][2] = exp2f((s[j][2] - mn1) * LOG2E_F); rs1 += s[j][2];
            s[j][3] = exp2f((s[j][3] - mn1) * LOG2E_F); rs1 += s[j][3];
        }
        #pragma unroll
        for (int off = 1; off < 4; off <<= 1) {
            rs0 += __shfl_xor_sync(0xffffffffu, rs0, off);
            rs1 += __shfl_xor_sync(0xffffffffu, rs1, off);
        }
        l0 = l0 * f0 + rs0; m0 = mn0;
        l1 = l1 * f1 + rs1; m1 = mn1;
        #pragma unroll
        for (int j = 0; j < 16; j++) {
            o[j][0] *= f0; o[j][1] *= f0;
            o[j][2] *= f1; o[j][3] *= f1;
        }

        uint32_t pah[4][4], pal[4][4];
        #pragma unroll
        for (int kc = 0; kc < 4; kc++) {
            split2(s[2 * kc][0],     s[2 * kc][1],     pah[kc][0], pal[kc][0]);
            split2(s[2 * kc][2],     s[2 * kc][3],     pah[kc][1], pal[kc][1]);
            split2(s[2 * kc + 1][0], s[2 * kc + 1][1], pah[kc][2], pal[kc][2]);
            split2(s[2 * kc + 1][2], s[2 * kc + 1][3], pah[kc][3], pal[kc][3]);
        }

        __syncthreads();
        load_conv(KVH, KVL, vbase + (size_t)(jt * 64) * QKV_N);
        __syncthreads();

        const int vrow_part = ((lane >> 3) & 1) * 8 + (lane & 7);
        const int vcol_part = (lane >> 4) * 8;
        #pragma unroll
        for (int kc = 0; kc < 4; kc++) {
            #pragma unroll
            for (int d16 = 0; d16 < 8; d16++) {
                uint32_t vh[4], vl[4];
                const uint32_t off = (kc * 16 + vrow_part) * SQB + (d16 * 16 + vcol_part) * 2;
                ldmx4t(vh, KVH_U + off);
                ldmx4t(vl, KVL_U + off);
                mma_bf16(o[2 * d16],     pah[kc], &vh[0]);
                mma_bf16(o[2 * d16 + 1], pah[kc], &vh[2]);
                mma_bf16(o[2 * d16],     pah[kc], &vl[0]);
                mma_bf16(o[2 * d16 + 1], pah[kc], &vl[2]);
                mma_bf16(o[2 * d16],     pal[kc], &vh[0]);
                mma_bf16(o[2 * d16 + 1], pal[kc], &vh[2]);
            }
        }
    }

    const float inv0 = 1.0f / l0, inv1 = 1.0f / l1;
    const size_t gr0 = row0 + qb * 64 + warp_m + r0;
    const size_t gr1 = gr0 + 8;
    #pragma unroll
    for (int j = 0; j < 16; j++) {
        const int col = h * D_HEAD + j * 8 + qq * 2;
        uint2 v0, v1;
        v0.x = tf32_bits(o[j][0] * inv0); v0.y = tf32_bits(o[j][1] * inv0);
        v1.x = tf32_bits(o[j][2] * inv1); v1.y = tf32_bits(o[j][3] * inv1);
        *(uint2*)&((uint32_t*)oatt)[gr0 * KDIM + col] = v0;
        *(uint2*)&((uint32_t*)oatt)[gr1 * KDIM + col] = v1;
    }
}

// ---------------------------------------------------------------------------
extern "C" void kernel_launch(void* const* d_in, const int* in_sizes, int n_in,
                              void* d_out, int out_size)
{
    const float* x    = (const float*)d_in[0];
    const float* Wqkv = (const float*)d_in[1];
    const float* bqkv = (const float*)d_in[2];
    const float* Wout = (const float*)d_in[3];
    const float* bout = (const float*)d_in[4];
    float* out = (float*)d_out;

    float *qkv, *a32, *wq32, *wo32;
    cudaGetSymbolAddress((void**)&qkv,  g_qkv);
    cudaGetSymbolAddress((void**)&a32,  g_a32);
    cudaGetSymbolAddress((void**)&wq32, g_wq32);
    cudaGetSymbolAddress((void**)&wo32, g_wo32);

    cudaFuncSetAttribute(gemm_tf32_kernel,
                         cudaFuncAttributeMaxDynamicSharedMemorySize, GEMM_SMEM);
    cudaFuncSetAttribute(attn_mma_kernel,
                         cudaFuncAttributeMaxDynamicSharedMemorySize, ATTN_SMEM);

    transpose_cvt<<<dim3(QKV_N / 32, KDIM / 32), dim3(32, 8)>>>(Wqkv, wq32, KDIM, QKV_N);
    transpose_cvt<<<dim3(D_MODEL / 32, KDIM / 32), dim3(32, 8)>>>(Wout, wo32, KDIM, D_MODEL);

    {
        const int n4 = ROWS * D_MODEL / 4;
        cvt_tf32<<<(n4 + 255) / 256, 256>>>(x, a32, n4);
    }
    gemm_tf32_kernel<<<dim3(QKV_N / GBN, ROWS / GBM), 256, GEMM_SMEM>>>(
        a32, wq32, bqkv, qkv, QKV_N);

    attn_mma_kernel<<<dim3(WINDOW / 64, NB, BATCH * N_HEADS), 128, ATTN_SMEM>>>(qkv, a32);

    gemm_tf32_kernel<<<dim3(D_MODEL / GBN, ROWS / GBM), 256, GEMM_SMEM>>>(
        a32, wo32, bout, out, D_MODEL);
}